// round 1
// baseline (speedup 1.0000x reference)
#include <cuda_runtime.h>
#include <cstdint>

// GraphSAGE fused layer kernel for GB300 (sm_103a).
// Per layer: A = [h_self || mean(h[adj])]  (N x 512),  out = A @ W + b (opt ReLU).
//
// Strategy: block = 64 rows x 256 cols (full N-dim). A-panel staged in smem,
// GEMM uses packed f32x2 FMAs (fma.rn.f32x2) for 2x fp32 throughput.

#define N_NODES 100000
#define DIM     256
#define KDIM    512           // 2*DIM
#define NNEIGH  10
#define BM      64
#define THREADS 256
#define BK      32

// Ping-pong scratch for intermediate layer outputs (no cudaMalloc allowed).
__device__ float g_buf0[(size_t)N_NODES * DIM];
__device__ float g_buf1[(size_t)N_NODES * DIM];

__device__ __forceinline__ unsigned long long pk2(float lo, float hi) {
    unsigned long long r;
    asm("mov.b64 %0, {%1, %2};" : "=l"(r) : "f"(lo), "f"(hi));
    return r;
}
__device__ __forceinline__ void upk2(unsigned long long v, float& lo, float& hi) {
    asm("mov.b64 {%0, %1}, %2;" : "=f"(lo), "=f"(hi) : "l"(v));
}
__device__ __forceinline__ void ffma2(unsigned long long& d, unsigned long long a,
                                      unsigned long long b) {
    // packed fp32x2 FMA: d.lo += a.lo*b.lo ; d.hi += a.hi*b.hi
    asm("fma.rn.f32x2 %0, %1, %2, %0;" : "+l"(d) : "l"(a), "l"(b));
}

template <bool RELU>
__global__ __launch_bounds__(THREADS, 1)
void sage_layer(const float* __restrict__ hin, const int* __restrict__ adj,
                const float* __restrict__ W, const float* __restrict__ bias,
                float* __restrict__ hout)
{
    extern __shared__ float smem[];
    float* Ap = smem;               // [BM][KDIM]  = 64 x 512 floats (128 KB)
    float* Ws = smem + BM * KDIM;   // [BK][DIM]   = 32 x 256 floats (32 KB)

    const int tid   = threadIdx.x;
    const int wid   = tid >> 5;     // warp id 0..7  -> row group (8 rows each)
    const int lane  = tid & 31;     // lane          -> col group
    const int m0blk = blockIdx.x * BM;

    // ---------------- Phase 1: build A panel (self || mean-neighbors) --------
    // Each warp owns 8 rows. Per row: two float4 column chunks
    //   cols [lane*4 .. lane*4+3] and [128+lane*4 .. 128+lane*4+3].
    #pragma unroll
    for (int rr = 0; rr < BM / 8; ++rr) {
        const int r   = wid * (BM / 8) + rr;
        const int row = m0blk + r;
        if (row < N_NODES) {
            const float4* hr = (const float4*)(hin + (size_t)row * DIM);
            float4 s0 = hr[lane];
            float4 s1 = hr[lane + 32];
            *(float4*)&Ap[r * KDIM + lane * 4]       = s0;
            *(float4*)&Ap[r * KDIM + 128 + lane * 4] = s1;

            float4 a0 = make_float4(0.f, 0.f, 0.f, 0.f);
            float4 a1 = make_float4(0.f, 0.f, 0.f, 0.f);
            const int* arow = adj + row * NNEIGH;
            #pragma unroll
            for (int j = 0; j < NNEIGH; ++j) {
                const int nb = arow[j];
                const float4* nr = (const float4*)(hin + (size_t)nb * DIM);
                float4 v0 = nr[lane];
                float4 v1 = nr[lane + 32];
                a0.x += v0.x; a0.y += v0.y; a0.z += v0.z; a0.w += v0.w;
                a1.x += v1.x; a1.y += v1.y; a1.z += v1.z; a1.w += v1.w;
            }
            const float inv = 1.0f / (float)NNEIGH;
            a0.x *= inv; a0.y *= inv; a0.z *= inv; a0.w *= inv;
            a1.x *= inv; a1.y *= inv; a1.z *= inv; a1.w *= inv;
            *(float4*)&Ap[r * KDIM + DIM + lane * 4]       = a0;
            *(float4*)&Ap[r * KDIM + DIM + 128 + lane * 4] = a1;
        }
    }
    __syncthreads();

    // ---------------- Phase 2: GEMM (A panel @ W) ----------------------------
    // Thread (wid, lane) computes rows m = wid*8..wid*8+7,
    // cols n = {lane*4..lane*4+3} U {128+lane*4..128+lane*4+3}.
    // Accumulators packed f32x2 along adjacent n.
    unsigned long long acc[8][4];
    #pragma unroll
    for (int i = 0; i < 8; ++i)
        #pragma unroll
        for (int j = 0; j < 4; ++j) acc[i][j] = 0ull;

    for (int kt = 0; kt < KDIM / BK; ++kt) {
        // Stage W tile [BK][DIM] into smem (coalesced float4).
        const float4* Wv  = (const float4*)(W + (size_t)kt * BK * DIM);
        float4*       Wsv = (float4*)Ws;
        #pragma unroll
        for (int it = 0; it < (BK * DIM / 4) / THREADS; ++it)
            Wsv[tid + it * THREADS] = Wv[tid + it * THREADS];
        __syncthreads();

        #pragma unroll
        for (int k = 0; k < BK; ++k) {
            unsigned long long aa[8];
            #pragma unroll
            for (int i = 0; i < 8; ++i) {
                // uniform per warp -> smem broadcast, conflict-free
                const float av = Ap[(wid * 8 + i) * KDIM + kt * BK + k];
                aa[i] = pk2(av, av);
            }
            const float4 b0 = *(const float4*)&Ws[k * DIM + lane * 4];
            const float4 b1 = *(const float4*)&Ws[k * DIM + 128 + lane * 4];
            unsigned long long bb[4];
            bb[0] = pk2(b0.x, b0.y); bb[1] = pk2(b0.z, b0.w);
            bb[2] = pk2(b1.x, b1.y); bb[3] = pk2(b1.z, b1.w);

            #pragma unroll
            for (int i = 0; i < 8; ++i)
                #pragma unroll
                for (int j = 0; j < 4; ++j)
                    ffma2(acc[i][j], aa[i], bb[j]);
        }
        __syncthreads();
    }

    // ---------------- Epilogue: bias (+ReLU) + store -------------------------
    const float4 bias0 = *(const float4*)&bias[lane * 4];
    const float4 bias1 = *(const float4*)&bias[128 + lane * 4];
    #pragma unroll
    for (int i = 0; i < 8; ++i) {
        const int row = m0blk + wid * 8 + i;
        if (row < N_NODES) {
            float4 o0, o1;
            upk2(acc[i][0], o0.x, o0.y);
            upk2(acc[i][1], o0.z, o0.w);
            upk2(acc[i][2], o1.x, o1.y);
            upk2(acc[i][3], o1.z, o1.w);
            o0.x += bias0.x; o0.y += bias0.y; o0.z += bias0.z; o0.w += bias0.w;
            o1.x += bias1.x; o1.y += bias1.y; o1.z += bias1.z; o1.w += bias1.w;
            if (RELU) {
                o0.x = fmaxf(o0.x, 0.f); o0.y = fmaxf(o0.y, 0.f);
                o0.z = fmaxf(o0.z, 0.f); o0.w = fmaxf(o0.w, 0.f);
                o1.x = fmaxf(o1.x, 0.f); o1.y = fmaxf(o1.y, 0.f);
                o1.z = fmaxf(o1.z, 0.f); o1.w = fmaxf(o1.w, 0.f);
            }
            *(float4*)(hout + (size_t)row * DIM + lane * 4)       = o0;
            *(float4*)(hout + (size_t)row * DIM + 128 + lane * 4) = o1;
        }
    }
}

extern "C" void kernel_launch(void* const* d_in, const int* in_sizes, int n_in,
                              void* d_out, int out_size)
{
    const float* x   = (const float*)d_in[0];
    const int*   adj = (const int*)  d_in[1];
    const float* W0  = (const float*)d_in[2];
    const float* b0  = (const float*)d_in[3];
    const float* W1  = (const float*)d_in[4];
    const float* b1  = (const float*)d_in[5];
    const float* W2  = (const float*)d_in[6];
    const float* b2  = (const float*)d_in[7];
    float* out = (float*)d_out;

    void *p0, *p1;
    cudaGetSymbolAddress(&p0, g_buf0);
    cudaGetSymbolAddress(&p1, g_buf1);
    float* h1 = (float*)p0;
    float* h2 = (float*)p1;

    const size_t shmem = (size_t)(BM * KDIM + BK * DIM) * sizeof(float); // 160 KB
    cudaFuncSetAttribute(sage_layer<true>,
                         cudaFuncAttributeMaxDynamicSharedMemorySize, (int)shmem);
    cudaFuncSetAttribute(sage_layer<false>,
                         cudaFuncAttributeMaxDynamicSharedMemorySize, (int)shmem);

    const int grid = (N_NODES + BM - 1) / BM;  // 1563

    sage_layer<true ><<<grid, THREADS, shmem>>>(x,  adj, W0, b0, h1);
    sage_layer<true ><<<grid, THREADS, shmem>>>(h1, adj, W1, b1, h2);
    sage_layer<false><<<grid, THREADS, shmem>>>(h2, adj, W2, b2, out);
}

// round 3
// speedup vs baseline: 1.7815x; 1.7815x over previous
#include <cuda_runtime.h>
#include <cuda_bf16.h>
#include <cstdint>

// GraphSAGE on GB300 via mma.sync bf16 hi/lo (3-MMA fp32 emulation).
// (tcgen05 unavailable: harness PTX target is base sm_103, no 'a' features.)
// Per layer: A = [h_self || mean(h[adj])] (N x 512), out = A @ W + b (opt ReLU).
// CTA: 128 rows x 256 cols, K in 8 chunks of 64, 512 threads (16 warps 4x4).

#define N_NODES 100000
#define DIM     256
#define KDIM    512
#define NNEIGH  10
#define BM      128
#define KC      64
#define NCHUNK  8
#define THREADS 512

// smem layout (bytes): A double buffer then W double buffer
#define ABUF    32768            // per A buffer: hi 16K + lo 16K
#define A_LO    16384
#define WBASE   65536
#define WBUF    65536            // per W buffer: hi 32K + lo 32K
#define W_LO    32768
#define SMEM_TOTAL (WBASE + 2 * WBUF)   // 196608

// -------- scratch (no cudaMalloc allowed) --------
__device__ float g_buf0[(size_t)N_NODES * DIM];
__device__ float g_buf1[(size_t)N_NODES * DIM];
// W fragments in exact mma B-frag order: [layer][ktile(32)][ntile(32)][lane(32)][2] u32
__device__ uint32_t g_wfrag_hi[3][32 * 32 * 32 * 2];
__device__ uint32_t g_wfrag_lo[3][32 * 32 * 32 * 2];

// -------- helpers --------
__device__ __forceinline__ uint32_t smem_u32(const void* p) {
    uint32_t a;
    asm("{ .reg .u64 t; cvta.to.shared.u64 t, %1; cvt.u32.u64 %0, t; }" : "=r"(a) : "l"(p));
    return a;
}
__device__ __forceinline__ uint32_t sw128(uint32_t off) {
    return off ^ ((off >> 3) & 0x70);
}
__device__ __forceinline__ uint32_t pack_bf2(float a, float b) {
    __nv_bfloat162 t = __floats2bfloat162_rn(a, b);
    return *reinterpret_cast<uint32_t*>(&t);
}
__device__ __forceinline__ void ldmat4(uint32_t* r, uint32_t addr) {
    asm volatile("ldmatrix.sync.aligned.m8n8.x4.shared.b16 {%0,%1,%2,%3}, [%4];"
                 : "=r"(r[0]), "=r"(r[1]), "=r"(r[2]), "=r"(r[3]) : "r"(addr));
}
__device__ __forceinline__ void mma16816(float* c, const uint32_t* a, uint32_t b0, uint32_t b1) {
    asm volatile("mma.sync.aligned.m16n8k16.row.col.f32.bf16.bf16.f32 "
                 "{%0,%1,%2,%3}, {%4,%5,%6,%7}, {%8,%9}, {%0,%1,%2,%3};"
                 : "+f"(c[0]), "+f"(c[1]), "+f"(c[2]), "+f"(c[3])
                 : "r"(a[0]), "r"(a[1]), "r"(a[2]), "r"(a[3]), "r"(b0), "r"(b1));
}
__device__ __forceinline__ void cpasync16(uint32_t smem_dst, const void* gsrc) {
    asm volatile("cp.async.cg.shared.global [%0], [%1], 16;"
                 :: "r"(smem_dst), "l"(gsrc) : "memory");
}
__device__ __forceinline__ void cpasync_commit() {
    asm volatile("cp.async.commit_group;" ::: "memory");
}
__device__ __forceinline__ void cpasync_wait0() {
    asm volatile("cp.async.wait_group 0;" ::: "memory");
}

// -------- W prep: hi/lo split into mma B-fragment order --------
// frag (kt, nt, lane): reg0 = {W[k0][n], W[k0+1][n]}, reg1 = {W[k0+8][n], W[k0+9][n]}
// with k0 = kt*16 + (lane&3)*2, n = nt*8 + (lane>>2).
__global__ void prep_wfrag(const float* __restrict__ W0, const float* __restrict__ W1,
                           const float* __restrict__ W2)
{
    int idx = blockIdx.x * blockDim.x + threadIdx.x;   // [layer][kt][nt][lane]
    if (idx >= 3 * 32 * 32 * 32) return;
    const int lane  = idx & 31;
    const int nt    = (idx >> 5) & 31;
    const int kt    = (idx >> 10) & 31;
    const int layer = idx >> 15;
    const float* W = layer == 0 ? W0 : (layer == 1 ? W1 : W2);
    const int k0 = kt * 16 + (lane & 3) * 2;
    const int n  = nt * 8 + (lane >> 2);

    float v[4] = { W[(k0 + 0) * DIM + n], W[(k0 + 1) * DIM + n],
                   W[(k0 + 8) * DIM + n], W[(k0 + 9) * DIM + n] };
    float hi[4], lo[4];
    #pragma unroll
    for (int i = 0; i < 4; ++i) {
        __nv_bfloat16 h = __float2bfloat16(v[i]);
        hi[i] = __bfloat162float(h);
        lo[i] = v[i] - hi[i];
    }
    const size_t base = ((size_t)(kt * 32 + nt) * 32 + lane) * 2;
    g_wfrag_hi[layer][base + 0] = pack_bf2(hi[0], hi[1]);
    g_wfrag_hi[layer][base + 1] = pack_bf2(hi[2], hi[3]);
    g_wfrag_lo[layer][base + 0] = pack_bf2(lo[0], lo[1]);
    g_wfrag_lo[layer][base + 1] = pack_bf2(lo[2], lo[3]);
}

// -------- fused SAGE layer --------
template <bool RELU>
__global__ __launch_bounds__(THREADS, 1)
void sage_mma(const float* __restrict__ hin, const int* __restrict__ adj,
              const uint32_t* __restrict__ wfh, const uint32_t* __restrict__ wfl,
              const float* __restrict__ bias, float* __restrict__ hout)
{
    extern __shared__ char smem[];
    const uint32_t sb = smem_u32(smem);
    const int tid  = threadIdx.x;
    const int lane = tid & 31;
    const int wid  = tid >> 5;
    const int wm   = wid & 3;     // warp m position (rows wm*32..+31)
    const int wn   = wid >> 2;    // warp n position (cols wn*64..+63)
    const int row0 = blockIdx.x * BM;

    // producer mapping: thread -> (row, quarter of 16 cols)
    const int pr = tid >> 2;         // 0..127
    const int pq = tid & 3;          // 0..3
    const int prow = row0 + pr;
    const bool pvalid = prow < N_NODES;

    float c[2][8][4];
    #pragma unroll
    for (int i = 0; i < 2; ++i)
        #pragma unroll
        for (int j = 0; j < 8; ++j)
            #pragma unroll
            for (int k = 0; k < 4; ++k) c[i][j][k] = 0.f;

    uint32_t ahi[8], alo[8];   // pending A fragment data (16 cols packed)

    // ---- produce chunk kc's A slice into ahi/alo regs ----
    auto produce = [&](int kc) {
        float v[16];
        const int src0 = (kc & 3) * KC + pq * 16;
        if (pvalid) {
            if (kc < 4) {
                const float4* s = (const float4*)(hin + (size_t)prow * DIM + src0);
                #pragma unroll
                for (int g = 0; g < 4; ++g) {
                    float4 q = s[g];
                    v[g * 4 + 0] = q.x; v[g * 4 + 1] = q.y;
                    v[g * 4 + 2] = q.z; v[g * 4 + 3] = q.w;
                }
            } else {
                #pragma unroll
                for (int i = 0; i < 16; ++i) v[i] = 0.f;
                const int* arow = adj + (size_t)prow * NNEIGH;
                #pragma unroll
                for (int j = 0; j < NNEIGH; ++j) {
                    const int nb = arow[j];
                    const float4* s = (const float4*)(hin + (size_t)nb * DIM + src0);
                    #pragma unroll
                    for (int g = 0; g < 4; ++g) {
                        float4 q = s[g];
                        v[g * 4 + 0] += q.x; v[g * 4 + 1] += q.y;
                        v[g * 4 + 2] += q.z; v[g * 4 + 3] += q.w;
                    }
                }
                #pragma unroll
                for (int i = 0; i < 16; ++i) v[i] *= (1.0f / NNEIGH);
            }
        } else {
            #pragma unroll
            for (int i = 0; i < 16; ++i) v[i] = 0.f;
        }
        #pragma unroll
        for (int p = 0; p < 8; ++p) {
            const float f0 = v[2 * p], f1 = v[2 * p + 1];
            const __nv_bfloat16 h0 = __float2bfloat16(f0), h1 = __float2bfloat16(f1);
            ahi[p] = pack_bf2(f0, f1);   // same rounding as h0,h1
            alo[p] = pack_bf2(f0 - __bfloat162float(h0), f1 - __bfloat162float(h1));
        }
    };

    // ---- store pending A regs into smem buffer (SW128 swizzled) ----
    auto storeA = [&](int kc) {
        char* Ab = smem + (kc & 1) * ABUF;
        const uint32_t off = (uint32_t)(pr * 128 + pq * 32);
        const uint32_t s0 = sw128(off), s1 = sw128(off + 16);
        *(uint4*)(Ab + s0)        = make_uint4(ahi[0], ahi[1], ahi[2], ahi[3]);
        *(uint4*)(Ab + s1)        = make_uint4(ahi[4], ahi[5], ahi[6], ahi[7]);
        *(uint4*)(Ab + A_LO + s0) = make_uint4(alo[0], alo[1], alo[2], alo[3]);
        *(uint4*)(Ab + A_LO + s1) = make_uint4(alo[4], alo[5], alo[6], alo[7]);
    };

    // ---- cp.async W-fragment chunk into smem buffer ----
    auto wcopy = [&](int kc) {
        const uint32_t dst = sb + WBASE + (kc & 1) * WBUF;
        const uint32_t* srcH = wfh + (size_t)kc * 8192;   // 32KB slab
        const uint32_t* srcL = wfl + (size_t)kc * 8192;
        #pragma unroll
        for (int i = 0; i < 4; ++i) {
            const int e = tid + i * THREADS;              // uint4 index, 2048 total
            cpasync16(dst + e * 16,        srcH + e * 4);
            cpasync16(dst + W_LO + e * 16, srcL + e * 4);
        }
        cpasync_commit();
    };

    // ================= pipeline =================
    wcopy(0);
    produce(0);
    cpasync_wait0();
    storeA(0);
    __syncthreads();

    for (int kc = 0; kc < NCHUNK; ++kc) {
        if (kc < NCHUNK - 1) {
            wcopy(kc + 1);       // into buf^1 (reads of kc-1 completed at last barrier)
            produce(kc + 1);     // LDGs issue early; math completes as data arrives
        }

        // ---- MMA on chunk kc ----
        const uint32_t Ab = sb + (kc & 1) * ABUF;
        const char*    Wp = smem + WBASE + (kc & 1) * WBUF;
        #pragma unroll
        for (int kt = 0; kt < 4; ++kt) {
            uint32_t ah0[4], ah1[4], al0[4], al1[4];
            const uint32_t off0 = (uint32_t)((wm * 32 + (lane & 15)) * 128 + kt * 32 + (lane >> 4) * 16);
            const uint32_t off1 = off0 + 16 * 128;
            ldmat4(ah0, Ab + sw128(off0));
            ldmat4(ah1, Ab + sw128(off1));
            ldmat4(al0, Ab + A_LO + sw128(off0));
            ldmat4(al1, Ab + A_LO + sw128(off1));

            const uint2* bh = (const uint2*)(Wp + ((size_t)(kt * 32 + wn * 8) * 32 + lane) * 8);
            const uint2* bl = (const uint2*)(Wp + W_LO + ((size_t)(kt * 32 + wn * 8) * 32 + lane) * 8);
            #pragma unroll
            for (int nt = 0; nt < 8; ++nt) {
                const uint2 h = bh[nt * 32];
                const uint2 l = bl[nt * 32];
                mma16816(c[0][nt], ah0, h.x, h.y);
                mma16816(c[1][nt], ah1, h.x, h.y);
                mma16816(c[0][nt], ah0, l.x, l.y);
                mma16816(c[1][nt], ah1, l.x, l.y);
                mma16816(c[0][nt], al0, h.x, h.y);
                mma16816(c[1][nt], al1, h.x, h.y);
            }
        }

        if (kc < NCHUNK - 1) {
            cpasync_wait0();
            __syncthreads();     // all MMA reads of buf^1's old data done; W data landed
            storeA(kc + 1);
            __syncthreads();     // A data visible before next MMA
        }
    }

    // ================= epilogue =================
    float2 bias2[8];
    #pragma unroll
    for (int nt = 0; nt < 8; ++nt)
        bias2[nt] = *(const float2*)&bias[wn * 64 + nt * 8 + (lane & 3) * 2];

    #pragma unroll
    for (int mt = 0; mt < 2; ++mt) {
        const int rbase = row0 + wm * 32 + mt * 16 + (lane >> 2);
        #pragma unroll
        for (int h = 0; h < 2; ++h) {
            const int row = rbase + h * 8;
            if (row < N_NODES) {
                #pragma unroll
                for (int nt = 0; nt < 8; ++nt) {
                    const int n = wn * 64 + nt * 8 + (lane & 3) * 2;
                    float2 o;
                    o.x = c[mt][nt][h * 2 + 0] + bias2[nt].x;
                    o.y = c[mt][nt][h * 2 + 1] + bias2[nt].y;
                    if (RELU) { o.x = fmaxf(o.x, 0.f); o.y = fmaxf(o.y, 0.f); }
                    *(float2*)(hout + (size_t)row * DIM + n) = o;
                }
            }
        }
    }
}

extern "C" void kernel_launch(void* const* d_in, const int* in_sizes, int n_in,
                              void* d_out, int out_size)
{
    const float* x   = (const float*)d_in[0];
    const int*   adj = (const int*)  d_in[1];
    const float* W0  = (const float*)d_in[2];
    const float* b0  = (const float*)d_in[3];
    const float* W1  = (const float*)d_in[4];
    const float* b1  = (const float*)d_in[5];
    const float* W2  = (const float*)d_in[6];
    const float* b2  = (const float*)d_in[7];
    float* out = (float*)d_out;

    void *p0, *p1, *pwh, *pwl;
    cudaGetSymbolAddress(&p0, g_buf0);
    cudaGetSymbolAddress(&p1, g_buf1);
    cudaGetSymbolAddress(&pwh, g_wfrag_hi);
    cudaGetSymbolAddress(&pwl, g_wfrag_lo);
    float* h1 = (float*)p0;
    float* h2 = (float*)p1;
    const uint32_t* wh = (const uint32_t*)pwh;
    const uint32_t* wl = (const uint32_t*)pwl;
    const size_t WSZ = 32 * 32 * 32 * 2;   // u32 per layer

    cudaFuncSetAttribute(sage_mma<true>,
                         cudaFuncAttributeMaxDynamicSharedMemorySize, SMEM_TOTAL);
    cudaFuncSetAttribute(sage_mma<false>,
                         cudaFuncAttributeMaxDynamicSharedMemorySize, SMEM_TOTAL);

    prep_wfrag<<<(3 * 32 * 32 * 32 + 255) / 256, 256>>>(W0, W1, W2);

    const int grid = (N_NODES + BM - 1) / BM;   // 782
    sage_mma<true ><<<grid, THREADS, SMEM_TOTAL>>>(x,  adj, wh,           wl,           b0, h1);
    sage_mma<true ><<<grid, THREADS, SMEM_TOTAL>>>(h1, adj, wh + WSZ,     wl + WSZ,     b1, h2);
    sage_mma<false><<<grid, THREADS, SMEM_TOTAL>>>(h2, adj, wh + 2 * WSZ, wl + 2 * WSZ, b2, out);
}

// round 4
// speedup vs baseline: 1.8679x; 1.0485x over previous
#include <cuda_runtime.h>
#include <cuda_bf16.h>
#include <cstdint>

// GraphSAGE on GB300 via mma.sync bf16 hi/lo (3-MMA fp32 emulation).
// R4: accumulator-independent MMA ordering (16-deep) + 1 barrier/chunk.

#define N_NODES 100000
#define DIM     256
#define KDIM    512
#define NNEIGH  10
#define BM      128
#define KC      64
#define NCHUNK  8
#define THREADS 512

#define ABUF    32768            // per A buffer: hi 16K + lo 16K
#define A_LO    16384
#define WBASE   65536
#define WBUF    65536            // per W buffer: hi 32K + lo 32K
#define W_LO    32768
#define SMEM_TOTAL (WBASE + 2 * WBUF)   // 196608

__device__ float g_buf0[(size_t)N_NODES * DIM];
__device__ float g_buf1[(size_t)N_NODES * DIM];
// W fragments in mma B-frag order: [layer][ktile(32)][ntile(32)][lane(32)][2] u32
__device__ uint32_t g_wfrag_hi[3][32 * 32 * 32 * 2];
__device__ uint32_t g_wfrag_lo[3][32 * 32 * 32 * 2];

__device__ __forceinline__ uint32_t smem_u32(const void* p) {
    uint32_t a;
    asm("{ .reg .u64 t; cvta.to.shared.u64 t, %1; cvt.u32.u64 %0, t; }" : "=r"(a) : "l"(p));
    return a;
}
__device__ __forceinline__ uint32_t sw128(uint32_t off) {
    return off ^ ((off >> 3) & 0x70);
}
__device__ __forceinline__ uint32_t pack_bf2(float a, float b) {
    __nv_bfloat162 t = __floats2bfloat162_rn(a, b);
    return *reinterpret_cast<uint32_t*>(&t);
}
__device__ __forceinline__ void ldmat4(uint32_t* r, uint32_t addr) {
    asm volatile("ldmatrix.sync.aligned.m8n8.x4.shared.b16 {%0,%1,%2,%3}, [%4];"
                 : "=r"(r[0]), "=r"(r[1]), "=r"(r[2]), "=r"(r[3]) : "r"(addr));
}
__device__ __forceinline__ void mma16816(float* c, const uint32_t* a, uint32_t b0, uint32_t b1) {
    asm volatile("mma.sync.aligned.m16n8k16.row.col.f32.bf16.bf16.f32 "
                 "{%0,%1,%2,%3}, {%4,%5,%6,%7}, {%8,%9}, {%0,%1,%2,%3};"
                 : "+f"(c[0]), "+f"(c[1]), "+f"(c[2]), "+f"(c[3])
                 : "r"(a[0]), "r"(a[1]), "r"(a[2]), "r"(a[3]), "r"(b0), "r"(b1));
}
__device__ __forceinline__ void cpasync16(uint32_t smem_dst, const void* gsrc) {
    asm volatile("cp.async.cg.shared.global [%0], [%1], 16;"
                 :: "r"(smem_dst), "l"(gsrc) : "memory");
}
__device__ __forceinline__ void cpasync_commit() {
    asm volatile("cp.async.commit_group;" ::: "memory");
}
__device__ __forceinline__ void cpasync_wait0() {
    asm volatile("cp.async.wait_group 0;" ::: "memory");
}

// -------- W prep: hi/lo split into mma B-fragment order --------
__global__ void prep_wfrag(const float* __restrict__ W0, const float* __restrict__ W1,
                           const float* __restrict__ W2)
{
    int idx = blockIdx.x * blockDim.x + threadIdx.x;   // [layer][kt][nt][lane]
    if (idx >= 3 * 32 * 32 * 32) return;
    const int lane  = idx & 31;
    const int nt    = (idx >> 5) & 31;
    const int kt    = (idx >> 10) & 31;
    const int layer = idx >> 15;
    const float* W = layer == 0 ? W0 : (layer == 1 ? W1 : W2);
    const int k0 = kt * 16 + (lane & 3) * 2;
    const int n  = nt * 8 + (lane >> 2);

    float v[4] = { W[(k0 + 0) * DIM + n], W[(k0 + 1) * DIM + n],
                   W[(k0 + 8) * DIM + n], W[(k0 + 9) * DIM + n] };
    float hi[4], lo[4];
    #pragma unroll
    for (int i = 0; i < 4; ++i) {
        __nv_bfloat16 h = __float2bfloat16(v[i]);
        hi[i] = __bfloat162float(h);
        lo[i] = v[i] - hi[i];
    }
    const size_t base = ((size_t)(kt * 32 + nt) * 32 + lane) * 2;
    g_wfrag_hi[layer][base + 0] = pack_bf2(hi[0], hi[1]);
    g_wfrag_hi[layer][base + 1] = pack_bf2(hi[2], hi[3]);
    g_wfrag_lo[layer][base + 0] = pack_bf2(lo[0], lo[1]);
    g_wfrag_lo[layer][base + 1] = pack_bf2(lo[2], lo[3]);
}

// -------- fused SAGE layer --------
template <bool RELU>
__global__ __launch_bounds__(THREADS, 1)
void sage_mma(const float* __restrict__ hin, const int* __restrict__ adj,
              const uint32_t* __restrict__ wfh, const uint32_t* __restrict__ wfl,
              const float* __restrict__ bias, float* __restrict__ hout)
{
    extern __shared__ char smem[];
    const uint32_t sb = smem_u32(smem);
    const int tid  = threadIdx.x;
    const int lane = tid & 31;
    const int wid  = tid >> 5;
    const int wm   = wid & 3;     // warp m position (rows wm*32..+31)
    const int wn   = wid >> 2;    // warp n position (cols wn*64..+63)
    const int row0 = blockIdx.x * BM;

    const int pr = tid >> 2;         // producer row 0..127
    const int pq = tid & 3;          // 16-col quarter
    const int prow = row0 + pr;
    const bool pvalid = prow < N_NODES;

    float c[2][8][4];
    #pragma unroll
    for (int i = 0; i < 2; ++i)
        #pragma unroll
        for (int j = 0; j < 8; ++j)
            #pragma unroll
            for (int k = 0; k < 4; ++k) c[i][j][k] = 0.f;

    uint32_t ahi[8], alo[8];

    auto produce = [&](int kc) {
        float v[16];
        const int src0 = (kc & 3) * KC + pq * 16;
        if (pvalid) {
            if (kc < 4) {
                const float4* s = (const float4*)(hin + (size_t)prow * DIM + src0);
                #pragma unroll
                for (int g = 0; g < 4; ++g) {
                    float4 q = s[g];
                    v[g * 4 + 0] = q.x; v[g * 4 + 1] = q.y;
                    v[g * 4 + 2] = q.z; v[g * 4 + 3] = q.w;
                }
            } else {
                #pragma unroll
                for (int i = 0; i < 16; ++i) v[i] = 0.f;
                const int* arow = adj + (size_t)prow * NNEIGH;
                #pragma unroll
                for (int j = 0; j < NNEIGH; ++j) {
                    const int nb = arow[j];
                    const float4* s = (const float4*)(hin + (size_t)nb * DIM + src0);
                    #pragma unroll
                    for (int g = 0; g < 4; ++g) {
                        float4 q = s[g];
                        v[g * 4 + 0] += q.x; v[g * 4 + 1] += q.y;
                        v[g * 4 + 2] += q.z; v[g * 4 + 3] += q.w;
                    }
                }
                #pragma unroll
                for (int i = 0; i < 16; ++i) v[i] *= (1.0f / NNEIGH);
            }
        } else {
            #pragma unroll
            for (int i = 0; i < 16; ++i) v[i] = 0.f;
        }
        #pragma unroll
        for (int p = 0; p < 8; ++p) {
            const float f0 = v[2 * p], f1 = v[2 * p + 1];
            const __nv_bfloat16 h0 = __float2bfloat16(f0), h1 = __float2bfloat16(f1);
            ahi[p] = pack_bf2(f0, f1);
            alo[p] = pack_bf2(f0 - __bfloat162float(h0), f1 - __bfloat162float(h1));
        }
    };

    auto storeA = [&](int kc) {
        char* Ab = smem + (kc & 1) * ABUF;
        const uint32_t off = (uint32_t)(pr * 128 + pq * 32);
        const uint32_t s0 = sw128(off), s1 = sw128(off + 16);
        *(uint4*)(Ab + s0)        = make_uint4(ahi[0], ahi[1], ahi[2], ahi[3]);
        *(uint4*)(Ab + s1)        = make_uint4(ahi[4], ahi[5], ahi[6], ahi[7]);
        *(uint4*)(Ab + A_LO + s0) = make_uint4(alo[0], alo[1], alo[2], alo[3]);
        *(uint4*)(Ab + A_LO + s1) = make_uint4(alo[4], alo[5], alo[6], alo[7]);
    };

    auto wcopy = [&](int kc) {
        const uint32_t dst = sb + WBASE + (kc & 1) * WBUF;
        const uint32_t* srcH = wfh + (size_t)kc * 8192;
        const uint32_t* srcL = wfl + (size_t)kc * 8192;
        #pragma unroll
        for (int i = 0; i < 4; ++i) {
            const int e = tid + i * THREADS;
            cpasync16(dst + e * 16,        srcH + e * 4);
            cpasync16(dst + W_LO + e * 16, srcL + e * 4);
        }
        cpasync_commit();
    };

    // ================= pipeline (1 barrier per chunk) =================
    wcopy(0);
    produce(0);
    storeA(0);
    cpasync_wait0();
    __syncthreads();

    for (int kc = 0; kc < NCHUNK; ++kc) {
        if (kc < NCHUNK - 1) {
            wcopy(kc + 1);       // writes W buf last read by MMA(kc-1) (barrier-ordered)
            produce(kc + 1);     // gather LDGs issue now, complete under MMA(kc)
        }

        // ---- MMA on chunk kc: variant-outer, 16 independent accumulators ----
        const uint32_t Ab = sb + (kc & 1) * ABUF;
        const char*    Wp = smem + WBASE + (kc & 1) * WBUF;
        #pragma unroll
        for (int kt = 0; kt < 4; ++kt) {
            uint32_t ah0[4], ah1[4], al0[4], al1[4];
            const uint32_t off0 = (uint32_t)((wm * 32 + (lane & 15)) * 128 + kt * 32 + (lane >> 4) * 16);
            const uint32_t off1 = off0 + 16 * 128;
            ldmat4(ah0, Ab + sw128(off0));
            ldmat4(ah1, Ab + sw128(off1));
            ldmat4(al0, Ab + A_LO + sw128(off0));
            ldmat4(al1, Ab + A_LO + sw128(off1));

            const uint2* bhp = (const uint2*)(Wp + ((size_t)(kt * 32 + wn * 8) * 32 + lane) * 8);
            const uint2* blp = (const uint2*)(Wp + W_LO + ((size_t)(kt * 32 + wn * 8) * 32 + lane) * 8);

            uint2 b[8];
            #pragma unroll
            for (int nt = 0; nt < 8; ++nt) b[nt] = bhp[nt * 32];
            #pragma unroll
            for (int nt = 0; nt < 8; ++nt) {         // hh block: 16 independent
                mma16816(c[0][nt], ah0, b[nt].x, b[nt].y);
                mma16816(c[1][nt], ah1, b[nt].x, b[nt].y);
            }
            #pragma unroll
            for (int nt = 0; nt < 8; ++nt) {         // lh block: 16 independent
                mma16816(c[0][nt], al0, b[nt].x, b[nt].y);
                mma16816(c[1][nt], al1, b[nt].x, b[nt].y);
            }
            #pragma unroll
            for (int nt = 0; nt < 8; ++nt) b[nt] = blp[nt * 32];
            #pragma unroll
            for (int nt = 0; nt < 8; ++nt) {         // hl block: 16 independent
                mma16816(c[0][nt], ah0, b[nt].x, b[nt].y);
                mma16816(c[1][nt], ah1, b[nt].x, b[nt].y);
            }
        }

        if (kc < NCHUNK - 1) {
            storeA(kc + 1);      // target buf last read by MMA(kc-1) (barrier-ordered)
            cpasync_wait0();
        }
        __syncthreads();
    }

    // ================= epilogue =================
    float2 bias2[8];
    #pragma unroll
    for (int nt = 0; nt < 8; ++nt)
        bias2[nt] = *(const float2*)&bias[wn * 64 + nt * 8 + (lane & 3) * 2];

    #pragma unroll
    for (int mt = 0; mt < 2; ++mt) {
        const int rbase = row0 + wm * 32 + mt * 16 + (lane >> 2);
        #pragma unroll
        for (int h = 0; h < 2; ++h) {
            const int row = rbase + h * 8;
            if (row < N_NODES) {
                #pragma unroll
                for (int nt = 0; nt < 8; ++nt) {
                    const int n = wn * 64 + nt * 8 + (lane & 3) * 2;
                    float2 o;
                    o.x = c[mt][nt][h * 2 + 0] + bias2[nt].x;
                    o.y = c[mt][nt][h * 2 + 1] + bias2[nt].y;
                    if (RELU) { o.x = fmaxf(o.x, 0.f); o.y = fmaxf(o.y, 0.f); }
                    *(float2*)(hout + (size_t)row * DIM + n) = o;
                }
            }
        }
    }
}

extern "C" void kernel_launch(void* const* d_in, const int* in_sizes, int n_in,
                              void* d_out, int out_size)
{
    const float* x   = (const float*)d_in[0];
    const int*   adj = (const int*)  d_in[1];
    const float* W0  = (const float*)d_in[2];
    const float* b0  = (const float*)d_in[3];
    const float* W1  = (const float*)d_in[4];
    const float* b1  = (const float*)d_in[5];
    const float* W2  = (const float*)d_in[6];
    const float* b2  = (const float*)d_in[7];
    float* out = (float*)d_out;

    void *p0, *p1, *pwh, *pwl;
    cudaGetSymbolAddress(&p0, g_buf0);
    cudaGetSymbolAddress(&p1, g_buf1);
    cudaGetSymbolAddress(&pwh, g_wfrag_hi);
    cudaGetSymbolAddress(&pwl, g_wfrag_lo);
    float* h1 = (float*)p0;
    float* h2 = (float*)p1;
    const uint32_t* wh = (const uint32_t*)pwh;
    const uint32_t* wl = (const uint32_t*)pwl;
    const size_t WSZ = 32 * 32 * 32 * 2;

    cudaFuncSetAttribute(sage_mma<true>,
                         cudaFuncAttributeMaxDynamicSharedMemorySize, SMEM_TOTAL);
    cudaFuncSetAttribute(sage_mma<false>,
                         cudaFuncAttributeMaxDynamicSharedMemorySize, SMEM_TOTAL);

    prep_wfrag<<<(3 * 32 * 32 * 32 + 255) / 256, 256>>>(W0, W1, W2);

    const int grid = (N_NODES + BM - 1) / BM;   // 782
    sage_mma<true ><<<grid, THREADS, SMEM_TOTAL>>>(x,  adj, wh,           wl,           b0, h1);
    sage_mma<true ><<<grid, THREADS, SMEM_TOTAL>>>(h1, adj, wh + WSZ,     wl + WSZ,     b1, h2);
    sage_mma<false><<<grid, THREADS, SMEM_TOTAL>>>(h2, adj, wh + 2 * WSZ, wl + 2 * WSZ, b2, out);
}

// round 5
// speedup vs baseline: 2.3420x; 1.2538x over previous
#include <cuda_runtime.h>
#include <cuda_bf16.h>
#include <cstdint>

// GraphSAGE on GB300 via mma.sync bf16 hi/lo (3-MMA fp32 emulation).
// R5: 2 CTAs/SM (BM=64, 256 thr, KC=32, 80KB smem) so one CTA's MMA covers
// the other's gather/barrier stalls.

#define N_NODES 100000
#define DIM     256
#define KDIM    512
#define NNEIGH  10
#define BM      64
#define KC      32
#define NCHUNK  16
#define THREADS 256

// smem layout (bytes)
// A buffers: 64 rows x 128B (hi cols 0..63 | lo cols 64..127), double buffered
#define ABUF    8192
#define WBASE   16384
#define WBUF    32768            // per W buffer: hi 16K + lo 16K
#define W_LO    16384
#define SMEM_TOTAL (WBASE + 2 * WBUF)   // 81920

__device__ float g_buf0[(size_t)N_NODES * DIM];
__device__ float g_buf1[(size_t)N_NODES * DIM];
// W fragments in mma B-frag order: [layer][ktile(32)][ntile(32)][lane(32)][2] u32
__device__ uint32_t g_wfrag_hi[3][32 * 32 * 32 * 2];
__device__ uint32_t g_wfrag_lo[3][32 * 32 * 32 * 2];

__device__ __forceinline__ uint32_t smem_u32(const void* p) {
    uint32_t a;
    asm("{ .reg .u64 t; cvta.to.shared.u64 t, %1; cvt.u32.u64 %0, t; }" : "=r"(a) : "l"(p));
    return a;
}
__device__ __forceinline__ uint32_t sw128(uint32_t off) {
    return off ^ ((off >> 3) & 0x70);
}
__device__ __forceinline__ uint32_t pack_bf2(float a, float b) {
    __nv_bfloat162 t = __floats2bfloat162_rn(a, b);
    return *reinterpret_cast<uint32_t*>(&t);
}
__device__ __forceinline__ void ldmat4(uint32_t* r, uint32_t addr) {
    asm volatile("ldmatrix.sync.aligned.m8n8.x4.shared.b16 {%0,%1,%2,%3}, [%4];"
                 : "=r"(r[0]), "=r"(r[1]), "=r"(r[2]), "=r"(r[3]) : "r"(addr));
}
__device__ __forceinline__ void mma16816(float* c, const uint32_t* a, uint32_t b0, uint32_t b1) {
    asm volatile("mma.sync.aligned.m16n8k16.row.col.f32.bf16.bf16.f32 "
                 "{%0,%1,%2,%3}, {%4,%5,%6,%7}, {%8,%9}, {%0,%1,%2,%3};"
                 : "+f"(c[0]), "+f"(c[1]), "+f"(c[2]), "+f"(c[3])
                 : "r"(a[0]), "r"(a[1]), "r"(a[2]), "r"(a[3]), "r"(b0), "r"(b1));
}
__device__ __forceinline__ void cpasync16(uint32_t smem_dst, const void* gsrc) {
    asm volatile("cp.async.cg.shared.global [%0], [%1], 16;"
                 :: "r"(smem_dst), "l"(gsrc) : "memory");
}
__device__ __forceinline__ void cpasync_commit() {
    asm volatile("cp.async.commit_group;" ::: "memory");
}
__device__ __forceinline__ void cpasync_wait0() {
    asm volatile("cp.async.wait_group 0;" ::: "memory");
}

// -------- W prep: hi/lo split into mma B-fragment order --------
__global__ void prep_wfrag(const float* __restrict__ W0, const float* __restrict__ W1,
                           const float* __restrict__ W2)
{
    int idx = blockIdx.x * blockDim.x + threadIdx.x;   // [layer][kt][nt][lane]
    if (idx >= 3 * 32 * 32 * 32) return;
    const int lane  = idx & 31;
    const int nt    = (idx >> 5) & 31;
    const int kt    = (idx >> 10) & 31;
    const int layer = idx >> 15;
    const float* W = layer == 0 ? W0 : (layer == 1 ? W1 : W2);
    const int k0 = kt * 16 + (lane & 3) * 2;
    const int n  = nt * 8 + (lane >> 2);

    float v[4] = { W[(k0 + 0) * DIM + n], W[(k0 + 1) * DIM + n],
                   W[(k0 + 8) * DIM + n], W[(k0 + 9) * DIM + n] };
    float hi[4], lo[4];
    #pragma unroll
    for (int i = 0; i < 4; ++i) {
        __nv_bfloat16 h = __float2bfloat16(v[i]);
        hi[i] = __bfloat162float(h);
        lo[i] = v[i] - hi[i];
    }
    const size_t base = ((size_t)(kt * 32 + nt) * 32 + lane) * 2;
    g_wfrag_hi[layer][base + 0] = pack_bf2(hi[0], hi[1]);
    g_wfrag_hi[layer][base + 1] = pack_bf2(hi[2], hi[3]);
    g_wfrag_lo[layer][base + 0] = pack_bf2(lo[0], lo[1]);
    g_wfrag_lo[layer][base + 1] = pack_bf2(lo[2], lo[3]);
}

// -------- fused SAGE layer --------
template <bool RELU>
__global__ __launch_bounds__(THREADS, 2)
void sage_mma(const float* __restrict__ hin, const int* __restrict__ adj,
              const uint32_t* __restrict__ wfh, const uint32_t* __restrict__ wfl,
              const float* __restrict__ bias, float* __restrict__ hout)
{
    extern __shared__ char smem[];
    const uint32_t sb = smem_u32(smem);
    const int tid  = threadIdx.x;
    const int lane = tid & 31;
    const int wid  = tid >> 5;
    const int wm   = wid & 1;     // warp m position (rows wm*32..+31)
    const int wn   = wid >> 1;    // warp n position (cols wn*64..+63)
    const int row0 = blockIdx.x * BM;

    const int pr = tid >> 2;         // producer row 0..63
    const int pq = tid & 3;          // 8-col quarter of the 32-col chunk
    const int prow = row0 + pr;
    const bool pvalid = prow < N_NODES;

    float c[2][8][4];
    #pragma unroll
    for (int i = 0; i < 2; ++i)
        #pragma unroll
        for (int j = 0; j < 8; ++j)
            #pragma unroll
            for (int k = 0; k < 4; ++k) c[i][j][k] = 0.f;

    uint32_t ahi[4], alo[4];         // pending 8 cols packed

    auto produce = [&](int kc) {
        float v[8];
        const int src0 = (kc & 7) * KC + pq * 8;
        if (pvalid) {
            if (kc < 8) {
                const float4* s = (const float4*)(hin + (size_t)prow * DIM + src0);
                float4 q0 = s[0], q1 = s[1];
                v[0] = q0.x; v[1] = q0.y; v[2] = q0.z; v[3] = q0.w;
                v[4] = q1.x; v[5] = q1.y; v[6] = q1.z; v[7] = q1.w;
            } else {
                #pragma unroll
                for (int i = 0; i < 8; ++i) v[i] = 0.f;
                const int* arow = adj + (size_t)prow * NNEIGH;
                #pragma unroll
                for (int j = 0; j < NNEIGH; ++j) {
                    const int nb = arow[j];
                    const float4* s = (const float4*)(hin + (size_t)nb * DIM + src0);
                    float4 q0 = s[0], q1 = s[1];
                    v[0] += q0.x; v[1] += q0.y; v[2] += q0.z; v[3] += q0.w;
                    v[4] += q1.x; v[5] += q1.y; v[6] += q1.z; v[7] += q1.w;
                }
                #pragma unroll
                for (int i = 0; i < 8; ++i) v[i] *= (1.0f / NNEIGH);
            }
        } else {
            #pragma unroll
            for (int i = 0; i < 8; ++i) v[i] = 0.f;
        }
        #pragma unroll
        for (int p = 0; p < 4; ++p) {
            const float f0 = v[2 * p], f1 = v[2 * p + 1];
            const __nv_bfloat16 h0 = __float2bfloat16(f0), h1 = __float2bfloat16(f1);
            ahi[p] = pack_bf2(f0, f1);
            alo[p] = pack_bf2(f0 - __bfloat162float(h0), f1 - __bfloat162float(h1));
        }
    };

    // A row layout: 128B per row = [hi 64B (32 cols) | lo 64B]
    auto storeA = [&](int kc) {
        char* Ab = smem + (kc & 1) * ABUF;
        const uint32_t offh = (uint32_t)(pr * 128 + pq * 16);
        *(uint4*)(Ab + sw128(offh))      = make_uint4(ahi[0], ahi[1], ahi[2], ahi[3]);
        *(uint4*)(Ab + sw128(offh + 64)) = make_uint4(alo[0], alo[1], alo[2], alo[3]);
    };

    auto wcopy = [&](int kc) {
        const uint32_t dst = sb + WBASE + (kc & 1) * WBUF;
        const uint32_t* srcH = wfh + (size_t)kc * 4096;   // 16KB slab per chunk
        const uint32_t* srcL = wfl + (size_t)kc * 4096;
        #pragma unroll
        for (int i = 0; i < 4; ++i) {
            const int e = tid + i * THREADS;              // uint4 idx, 1024 total
            cpasync16(dst + e * 16,        srcH + e * 4);
            cpasync16(dst + W_LO + e * 16, srcL + e * 4);
        }
        cpasync_commit();
    };

    // ================= pipeline (1 barrier per chunk) =================
    wcopy(0);
    produce(0);
    storeA(0);
    cpasync_wait0();
    __syncthreads();

    for (int kc = 0; kc < NCHUNK; ++kc) {
        if (kc < NCHUNK - 1) {
            wcopy(kc + 1);
            produce(kc + 1);     // gather LDGs complete under MMA(kc)
        }

        const uint32_t Ab = sb + (kc & 1) * ABUF;
        const char*    Wp = smem + WBASE + (kc & 1) * WBUF;
        #pragma unroll
        for (int kt = 0; kt < 2; ++kt) {
            uint32_t ah0[4], ah1[4], al0[4], al1[4];
            const uint32_t off0 = (uint32_t)((wm * 32 + (lane & 15)) * 128 + kt * 32 + (lane >> 4) * 16);
            const uint32_t off1 = off0 + 16 * 128;
            ldmat4(ah0, Ab + sw128(off0));
            ldmat4(ah1, Ab + sw128(off1));
            ldmat4(al0, Ab + sw128(off0 + 64));
            ldmat4(al1, Ab + sw128(off1 + 64));

            const uint2* bhp = (const uint2*)(Wp + ((size_t)(kt * 32 + wn * 8) * 32 + lane) * 8);
            const uint2* blp = (const uint2*)(Wp + W_LO + ((size_t)(kt * 32 + wn * 8) * 32 + lane) * 8);

            uint2 b[8];
            #pragma unroll
            for (int nt = 0; nt < 8; ++nt) b[nt] = bhp[nt * 32];
            #pragma unroll
            for (int nt = 0; nt < 8; ++nt) {         // hh: 16 independent
                mma16816(c[0][nt], ah0, b[nt].x, b[nt].y);
                mma16816(c[1][nt], ah1, b[nt].x, b[nt].y);
            }
            #pragma unroll
            for (int nt = 0; nt < 8; ++nt) {         // lh: 16 independent
                mma16816(c[0][nt], al0, b[nt].x, b[nt].y);
                mma16816(c[1][nt], al1, b[nt].x, b[nt].y);
            }
            #pragma unroll
            for (int nt = 0; nt < 8; ++nt) b[nt] = blp[nt * 32];
            #pragma unroll
            for (int nt = 0; nt < 8; ++nt) {         // hl: 16 independent
                mma16816(c[0][nt], ah0, b[nt].x, b[nt].y);
                mma16816(c[1][nt], ah1, b[nt].x, b[nt].y);
            }
        }

        if (kc < NCHUNK - 1) {
            storeA(kc + 1);      // buffer last read in MMA(kc-1), barrier-ordered
            cpasync_wait0();
        }
        __syncthreads();
    }

    // ================= epilogue =================
    float2 bias2[8];
    #pragma unroll
    for (int nt = 0; nt < 8; ++nt)
        bias2[nt] = *(const float2*)&bias[wn * 64 + nt * 8 + (lane & 3) * 2];

    #pragma unroll
    for (int mt = 0; mt < 2; ++mt) {
        const int rbase = row0 + wm * 32 + mt * 16 + (lane >> 2);
        #pragma unroll
        for (int h = 0; h < 2; ++h) {
            const int row = rbase + h * 8;
            if (row < N_NODES) {
                #pragma unroll
                for (int nt = 0; nt < 8; ++nt) {
                    const int n = wn * 64 + nt * 8 + (lane & 3) * 2;
                    float2 o;
                    o.x = c[mt][nt][h * 2 + 0] + bias2[nt].x;
                    o.y = c[mt][nt][h * 2 + 1] + bias2[nt].y;
                    if (RELU) { o.x = fmaxf(o.x, 0.f); o.y = fmaxf(o.y, 0.f); }
                    *(float2*)(hout + (size_t)row * DIM + n) = o;
                }
            }
        }
    }
}

extern "C" void kernel_launch(void* const* d_in, const int* in_sizes, int n_in,
                              void* d_out, int out_size)
{
    const float* x   = (const float*)d_in[0];
    const int*   adj = (const int*)  d_in[1];
    const float* W0  = (const float*)d_in[2];
    const float* b0  = (const float*)d_in[3];
    const float* W1  = (const float*)d_in[4];
    const float* b1  = (const float*)d_in[5];
    const float* W2  = (const float*)d_in[6];
    const float* b2  = (const float*)d_in[7];
    float* out = (float*)d_out;

    void *p0, *p1, *pwh, *pwl;
    cudaGetSymbolAddress(&p0, g_buf0);
    cudaGetSymbolAddress(&p1, g_buf1);
    cudaGetSymbolAddress(&pwh, g_wfrag_hi);
    cudaGetSymbolAddress(&pwl, g_wfrag_lo);
    float* h1 = (float*)p0;
    float* h2 = (float*)p1;
    const uint32_t* wh = (const uint32_t*)pwh;
    const uint32_t* wl = (const uint32_t*)pwl;
    const size_t WSZ = 32 * 32 * 32 * 2;

    cudaFuncSetAttribute(sage_mma<true>,
                         cudaFuncAttributeMaxDynamicSharedMemorySize, SMEM_TOTAL);
    cudaFuncSetAttribute(sage_mma<false>,
                         cudaFuncAttributeMaxDynamicSharedMemorySize, SMEM_TOTAL);

    prep_wfrag<<<(3 * 32 * 32 * 32 + 255) / 256, 256>>>(W0, W1, W2);

    const int grid = (N_NODES + BM - 1) / BM;   // 1563
    sage_mma<true ><<<grid, THREADS, SMEM_TOTAL>>>(x,  adj, wh,           wl,           b0, h1);
    sage_mma<true ><<<grid, THREADS, SMEM_TOTAL>>>(h1, adj, wh + WSZ,     wl + WSZ,     b1, h2);
    sage_mma<false><<<grid, THREADS, SMEM_TOTAL>>>(h2, adj, wh + 2 * WSZ, wl + 2 * WSZ, b2, out);
}